// round 16
// baseline (speedup 1.0000x reference)
#include <cuda_runtime.h>
#include <cuda_fp16.h>
#include <cstdint>

#define SDIM 2048
#define HDIM 1024
#define RDIM 65536

// ---- gemm tiling ----
#define ROWS_CTA 64
#define NT 256                 // o-cols per o-iter
#define GSTEPS 128             // 4 o-iters x 32 k-steps (BK=32)

// ---- smem layout (bytes). 80B padded rows (64B data + 16B pad) ----
#define STRIDE 80
#define SA    0                // A: 64 rows x 80B = 5120 (fp16)
#define SB    5120             // B: 256 rows x 80B = 20480 (fp16)
#define STAGE_SZ 25600
#define NSTG 3
#define SM_BIAS (NSTG * STAGE_SZ)   // 76800
#define SM_V    (SM_BIAS + 4096)
#define SM_ROW  (SM_V + 4096)
#define SMEM_TOTAL (SM_ROW + 256)   // 85248

__device__ __align__(16) __half g_we_h[(size_t)HDIM * HDIM];  // We rounded to fp16 (2MB)
__device__ float g_bias_part[8][32 * HDIM];                   // k-chunk partials of bias GEMV
__device__ float g_logits[RDIM];

// ---------------- helpers ----------------
__device__ __forceinline__ uint32_t smem_u32(const void* p) {
    uint32_t a;
    asm("{ .reg .u64 t; cvta.to.shared.u64 t, %1; cvt.u32.u64 %0, t; }" : "=r"(a) : "l"(p));
    return a;
}
__device__ __forceinline__ void cp16(uint32_t dst, const void* src) {
    asm volatile("cp.async.cg.shared.global [%0], [%1], 16;" :: "r"(dst), "l"(src) : "memory");
}
__device__ __forceinline__ void ldsm4(uint32_t* r, uint32_t a) {
    asm volatile("ldmatrix.sync.aligned.m8n8.x4.shared.b16 {%0,%1,%2,%3}, [%4];"
                 : "=r"(r[0]), "=r"(r[1]), "=r"(r[2]), "=r"(r[3]) : "r"(a));
}
__device__ __forceinline__ void mma16816(float* c, const uint32_t* a, const uint32_t* b) {
    asm volatile("mma.sync.aligned.m16n8k16.row.col.f32.f16.f16.f32 "
                 "{%0,%1,%2,%3}, {%4,%5,%6,%7}, {%8,%9}, {%0,%1,%2,%3};"
                 : "+f"(c[0]), "+f"(c[1]), "+f"(c[2]), "+f"(c[3])
                 : "r"(a[0]), "r"(a[1]), "r"(a[2]), "r"(a[3]), "r"(b[0]), "r"(b[1]));
}
// accurate fast tanh: sign(x)*(1 - 2/(e^{2|x|}+1)), 2 MUFU, ~1e-6 err
__device__ __forceinline__ float ftanh(float x) {
    float ax = fminf(fabsf(x), 12.0f);
    float e;
    asm("ex2.approx.f32 %0, %1;" : "=f"(e) : "f"(ax * 2.885390082f));
    float r;
    asm("rcp.approx.f32 %0, %1;" : "=f"(r) : "f"(e + 1.0f));
    return copysignf(fmaf(-2.0f, r, 1.0f), x);
}

// ---------------- prep ----------------
// blocks [0,256): We -> fp16 (16 floats/thread for MLP)
// blocks [256,512): bias GEMV partial: block (ob, kc) computes
//   g_bias_part[kc][b][o0+ol] = sum_{k in chunk} hidden[b][k] * W[o][k]  (+ b_attn at kc=0)
__global__ void __launch_bounds__(256) prep_kernel(const float* __restrict__ W,
                                                   const float* __restrict__ hidden,
                                                   const float* __restrict__ b_attn) {
    const int bid = blockIdx.x, tid = threadIdx.x;
    if (bid < 256) {
        const size_t base = ((size_t)bid * 256 + tid) * 16;
        const int o = (int)(base >> 10), k = (int)(base & 1023);
        const float4* p = (const float4*)(W + (size_t)o * 2 * HDIM + HDIM + k);
        const float4 f0 = p[0], f1 = p[1], f2 = p[2], f3 = p[3];
        const float f[16] = {f0.x, f0.y, f0.z, f0.w, f1.x, f1.y, f1.z, f1.w,
                             f2.x, f2.y, f2.z, f2.w, f3.x, f3.y, f3.z, f3.w};
        __half h[16];
#pragma unroll
        for (int i = 0; i < 16; i++) h[i] = __float2half_rn(f[i]);
        *(uint4*)(g_we_h + base)     = ((const uint4*)h)[0];
        *(uint4*)(g_we_h + base + 8) = ((const uint4*)h)[1];
    } else {
        __shared__ float sW[32 * 129];
        __shared__ float sH[32 * 129];
        const int bid2 = bid - 256;          // 0..255
        const int kc = bid2 & 7, ob = bid2 >> 3;
        const int o0 = ob * 32, k0 = kc * 128;
        const int ol = tid & 31;
        const int b0 = tid >> 5;
#pragma unroll
        for (int i = 0; i < 4; i++) {
            const int idx = tid + i * 256;            // 1024 float4 total
            const int row = idx >> 5, c4 = (idx & 31) * 4;
            const float4 w = *(const float4*)(W + (size_t)(o0 + row) * 2 * HDIM + k0 + c4);
            sW[row * 129 + c4 + 0] = w.x;
            sW[row * 129 + c4 + 1] = w.y;
            sW[row * 129 + c4 + 2] = w.z;
            sW[row * 129 + c4 + 3] = w.w;
            const float4 h = *(const float4*)(hidden + (size_t)row * HDIM + k0 + c4);
            sH[row * 129 + c4 + 0] = h.x;
            sH[row * 129 + c4 + 1] = h.y;
            sH[row * 129 + c4 + 2] = h.z;
            sH[row * 129 + c4 + 3] = h.w;
        }
        __syncthreads();
        float acc[4] = {0.f, 0.f, 0.f, 0.f};
#pragma unroll 4
        for (int k = 0; k < 128; k++) {
            const float w = sW[ol * 129 + k];
#pragma unroll
            for (int j = 0; j < 4; j++)
                acc[j] = fmaf(w, sH[(b0 + 8 * j) * 129 + k], acc[j]);
        }
        const float ba = (kc == 0) ? b_attn[o0 + ol] : 0.0f;
#pragma unroll
        for (int j = 0; j < 4; j++)
            g_bias_part[kc][(b0 + 8 * j) * HDIM + o0 + ol] = acc[j] + ba;
    }
}

// ---------------- gemm pieces ----------------
// A: thread (row = tid>>2, seg = tid&3) loads 8 fp32 of enc row
__device__ __forceinline__ void ldgA(float* af, const float* __restrict__ enc, int gs, int r0) {
    const int tid = threadIdx.x;
    const int row = tid >> 2, seg = tid & 3;
    const int k0 = (gs & 31) * 32;
    const float* p = enc + (size_t)(r0 + row) * HDIM + k0 + seg * 8;
    *(float4*)(af)     = *(const float4*)(p);
    *(float4*)(af + 4) = *(const float4*)(p + 4);
}
__device__ __forceinline__ void stsA(const float* af, char* smem, int gs) {
    const int tid = threadIdx.x;
    const int row = tid >> 2, seg = tid & 3;
    __half h[8];
#pragma unroll
    for (int i = 0; i < 8; i++) h[i] = __float2half_rn(af[i]);
    char* b = smem + (gs % NSTG) * STAGE_SZ + SA + row * STRIDE + seg * 16;
    *(uint4*)(b) = *(const uint4*)h;
}
__device__ __forceinline__ void cpB(uint32_t sb, int gs) {
    const int tid = threadIdx.x;
    const int k0 = (gs & 31) * 32, o0 = (gs >> 5) * NT;
    const uint32_t base = sb + (gs % NSTG) * STAGE_SZ + SB;
#pragma unroll
    for (int i = 0; i < 4; i++) {
        const int c = tid + i * 256;
        const int row = c >> 2, seg = c & 3;
        cp16(base + row * STRIDE + seg * 16,
             g_we_h + (size_t)(o0 + row) * HDIM + k0 + seg * 8);
    }
}

__global__ void __launch_bounds__(256, 2)
gemm_kernel(const float* __restrict__ enc, const float* __restrict__ v) {
    extern __shared__ char smem[];
    const uint32_t sb = smem_u32(smem);
    const int tid = threadIdx.x;
    const int lane = tid & 31, warp = tid >> 5;
    const int warp_m = (warp >> 2) * 32;      // 2 warps over M (2 mt of m16)
    const int warp_n = (warp & 3) * 64;       // 4 warps over N
    const int r0 = blockIdx.x * ROWS_CTA;
    const int bb = r0 >> 11;

    float* s_bias = (float*)(smem + SM_BIAS);
    float* s_v    = (float*)(smem + SM_V);
    float* s_row  = (float*)(smem + SM_ROW);
    for (int i = tid; i < HDIM; i += 256) {
        float bsum = 0.0f;
#pragma unroll
        for (int kc = 0; kc < 8; kc++)
            bsum += g_bias_part[kc][bb * HDIM + i];
        s_bias[i] = bsum;
        s_v[i] = v[i];
    }
    if (tid < ROWS_CTA) s_row[tid] = 0.0f;

    // ldmatrix per-lane address components
    const int q = lane >> 3, rr = lane & 7;
    const int a_row_off = (q & 1) * 8 + rr;
    const int a_k_off   = (q >> 1) * 8;
    const int b_row_off = (q >> 1) * 8 + rr;
    const int b_k_off   = (q & 1) * 8;

    float af[8];
    // prologue: stages 0,1 fully in flight; A(2) in regs
    ldgA(af, enc, 0, r0);
    stsA(af, smem, 0);
    ldgA(af, enc, 1, r0);
    stsA(af, smem, 1);
    cpB(sb, 0);
    asm volatile("cp.async.commit_group;" ::: "memory");
    cpB(sb, 1);
    asm volatile("cp.async.commit_group;" ::: "memory");
    ldgA(af, enc, 2, r0);

    float part[4] = {0.f, 0.f, 0.f, 0.f};
    float acc[2][8][4];

    for (int gs = 0; gs < GSTEPS; gs++) {
        asm volatile("cp.async.wait_group 1;" ::: "memory");
        __syncthreads();

        // issue next-stage traffic before compute (single sync per stage)
        if (gs + 2 < GSTEPS) stsA(af, smem, gs + 2);
        if (gs + 3 < GSTEPS) ldgA(af, enc, gs + 3, r0);
        if (gs + 2 < GSTEPS) cpB(sb, gs + 2);
        asm volatile("cp.async.commit_group;" ::: "memory");

        if ((gs & 31) == 0) {
#pragma unroll
            for (int mt = 0; mt < 2; mt++)
#pragma unroll
                for (int nt = 0; nt < 8; nt++)
#pragma unroll
                    for (int e = 0; e < 4; e++) acc[mt][nt][e] = 0.0f;
        }

        const uint32_t stg = sb + (uint32_t)(gs % NSTG) * STAGE_SZ;
        const uint32_t a_base = stg + SA;
        const uint32_t b_base = stg + SB + (warp_n + b_row_off) * STRIDE;
#pragma unroll
        for (int kh = 0; kh < 2; kh++) {
            const int kk = kh * 16;
            uint32_t ah[2][4];
#pragma unroll
            for (int mt = 0; mt < 2; mt++) {
                const uint32_t ra = a_base + (warp_m + mt * 16 + a_row_off) * STRIDE
                                  + (kk + a_k_off) * 2;
                ldsm4(ah[mt], ra);
            }
#pragma unroll
            for (int p = 0; p < 4; p++) {
                uint32_t bh[4];
                const uint32_t rb = b_base + p * 16 * STRIDE + (kk + b_k_off) * 2;
                ldsm4(bh, rb);
#pragma unroll
                for (int mt = 0; mt < 2; mt++) {
                    mma16816(acc[mt][2 * p],     ah[mt], bh);
                    mma16816(acc[mt][2 * p + 1], ah[mt], bh + 2);
                }
            }
        }

        if ((gs & 31) == 31) {
            const int oo = (gs >> 5) * NT + warp_n + (lane & 3) * 2;
#pragma unroll
            for (int mt = 0; mt < 2; mt++)
#pragma unroll
                for (int nt = 0; nt < 8; nt++) {
                    const int o0e = oo + nt * 8;
                    const float b0 = s_bias[o0e], b1 = s_bias[o0e + 1];
                    const float v0 = s_v[o0e],    v1 = s_v[o0e + 1];
                    const float* c = acc[mt][nt];
                    part[mt * 2 + 0] += ftanh(c[0] + b0) * v0 + ftanh(c[1] + b1) * v1;
                    part[mt * 2 + 1] += ftanh(c[2] + b0) * v0 + ftanh(c[3] + b1) * v1;
                }
        }
    }

    // reduce 4-lane groups sharing each row, then combine across n-warps
#pragma unroll
    for (int i = 0; i < 4; i++) {
        float s = part[i];
        s += __shfl_xor_sync(0xFFFFFFFFu, s, 1);
        s += __shfl_xor_sync(0xFFFFFFFFu, s, 2);
        if ((lane & 3) == 0) {
            const int row = warp_m + (i >> 1) * 16 + (i & 1) * 8 + (lane >> 2);
            atomicAdd(&s_row[row], s);
        }
    }
    __syncthreads();
    if (tid < ROWS_CTA) g_logits[r0 + tid] = s_row[tid];
}

// ---------------- softmax over s per batch (warp-shuffle reductions) ----------------
__global__ void softmax_kernel(float* __restrict__ out) {
    __shared__ float red[8];
    const int b = blockIdx.x, tid = threadIdx.x;
    const int lane = tid & 31, wid = tid >> 5;
    const float* lg = g_logits + (size_t)b * SDIM;
    float vals[8];
    float lmax = -1e30f;
#pragma unroll
    for (int i = 0; i < 8; i++) {
        vals[i] = lg[tid + i * 256];
        lmax = fmaxf(lmax, vals[i]);
    }
#pragma unroll
    for (int off = 16; off > 0; off >>= 1)
        lmax = fmaxf(lmax, __shfl_xor_sync(0xFFFFFFFFu, lmax, off));
    if (lane == 0) red[wid] = lmax;
    __syncthreads();
    float gmax = red[0];
#pragma unroll
    for (int w = 1; w < 8; w++) gmax = fmaxf(gmax, red[w]);

    float lsum = 0.0f;
#pragma unroll
    for (int i = 0; i < 8; i++) {
        vals[i] = expf(vals[i] - gmax);
        lsum += vals[i];
    }
#pragma unroll
    for (int off = 16; off > 0; off >>= 1)
        lsum += __shfl_xor_sync(0xFFFFFFFFu, lsum, off);
    __syncthreads();
    if (lane == 0) red[wid] = lsum;
    __syncthreads();
    float gsum = 0.0f;
#pragma unroll
    for (int w = 0; w < 8; w++) gsum += red[w];

    const float inv = 1.0f / gsum;
#pragma unroll
    for (int i = 0; i < 8; i++)
        out[(size_t)b * SDIM + tid + i * 256] = vals[i] * inv;
}

// ---------------- launch ----------------
extern "C" void kernel_launch(void* const* d_in, const int* in_sizes, int n_in,
                              void* d_out, int out_size) {
    const float* hidden = (const float*)d_in[0];
    const float* enc    = (const float*)d_in[1];
    const float* W      = (const float*)d_in[2];
    const float* b_attn = (const float*)d_in[3];
    const float* v      = (const float*)d_in[4];
    float* out = (float*)d_out;

    cudaFuncSetAttribute(gemm_kernel, cudaFuncAttributeMaxDynamicSharedMemorySize, SMEM_TOTAL);
    prep_kernel<<<512, 256>>>(W, hidden, b_attn);
    gemm_kernel<<<RDIM / ROWS_CTA, 256, SMEM_TOTAL>>>(enc, v);
    softmax_kernel<<<32, 256>>>(out);
}

// round 17
// speedup vs baseline: 1.0079x; 1.0079x over previous
#include <cuda_runtime.h>
#include <cuda_fp16.h>
#include <cstdint>

#define SDIM 2048
#define HDIM 1024
#define RDIM 65536

// ---- gemm tiling ----
#define ROWS_CTA 64
#define NT 256                 // o-cols per o-iter
#define GSTEPS 128             // 4 o-iters x 32 k-steps (BK=32)

// ---- smem layout (bytes). 80B padded rows (64B data + 16B pad) ----
#define STRIDE 80
#define SA    0                // A: 64 rows x 80B = 5120 (fp16)
#define SB    5120             // B: 256 rows x 80B = 20480 (fp16)
#define STAGE_SZ 25600
#define NSTG 3
#define SM_BIAS (NSTG * STAGE_SZ)   // 76800
#define SM_V    (SM_BIAS + 4096)
#define SM_ROW  (SM_V + 4096)
#define SMEM_TOTAL (SM_ROW + 256)   // 85248

__device__ __align__(16) __half g_we_h[(size_t)HDIM * HDIM];  // We rounded to fp16 (2MB)
__device__ float g_bias_part[8][32 * HDIM];                   // k-chunk partials of bias GEMV
__device__ float g_logits[RDIM];

// ---------------- helpers ----------------
__device__ __forceinline__ uint32_t smem_u32(const void* p) {
    uint32_t a;
    asm("{ .reg .u64 t; cvta.to.shared.u64 t, %1; cvt.u32.u64 %0, t; }" : "=r"(a) : "l"(p));
    return a;
}
__device__ __forceinline__ void cp16(uint32_t dst, const void* src) {
    asm volatile("cp.async.cg.shared.global [%0], [%1], 16;" :: "r"(dst), "l"(src) : "memory");
}
__device__ __forceinline__ void ldsm4(uint32_t* r, uint32_t a) {
    asm volatile("ldmatrix.sync.aligned.m8n8.x4.shared.b16 {%0,%1,%2,%3}, [%4];"
                 : "=r"(r[0]), "=r"(r[1]), "=r"(r[2]), "=r"(r[3]) : "r"(a));
}
__device__ __forceinline__ void mma16816(float* c, const uint32_t* a, const uint32_t* b) {
    asm volatile("mma.sync.aligned.m16n8k16.row.col.f32.f16.f16.f32 "
                 "{%0,%1,%2,%3}, {%4,%5,%6,%7}, {%8,%9}, {%0,%1,%2,%3};"
                 : "+f"(c[0]), "+f"(c[1]), "+f"(c[2]), "+f"(c[3])
                 : "r"(a[0]), "r"(a[1]), "r"(a[2]), "r"(a[3]), "r"(b[0]), "r"(b[1]));
}
// accurate fast tanh: sign(x)*(1 - 2/(e^{2|x|}+1)), 2 MUFU, ~1e-6 err
__device__ __forceinline__ float ftanh(float x) {
    float ax = fminf(fabsf(x), 12.0f);
    float e;
    asm("ex2.approx.f32 %0, %1;" : "=f"(e) : "f"(ax * 2.885390082f));
    float r;
    asm("rcp.approx.f32 %0, %1;" : "=f"(r) : "f"(e + 1.0f));
    return copysignf(fmaf(-2.0f, r, 1.0f), x);
}

// ---------------- prep ----------------
// blocks [0,512): We -> fp16 (8 floats/thread, 512 blocks — measured-best occupancy)
// blocks [512,768): bias GEMV partial: block (ob, kc) computes
//   g_bias_part[kc][b][o0+ol] = sum_{k in chunk} hidden[b][k] * W[o][k]  (+ b_attn at kc=0)
__global__ void __launch_bounds__(256) prep_kernel(const float* __restrict__ W,
                                                   const float* __restrict__ hidden,
                                                   const float* __restrict__ b_attn) {
    const int bid = blockIdx.x, tid = threadIdx.x;
    if (bid < 512) {
        const size_t base = ((size_t)bid * 256 + tid) * 8;
        const int o = (int)(base >> 10), k = (int)(base & 1023);
        const float4* p = (const float4*)(W + (size_t)o * 2 * HDIM + HDIM + k);
        const float4 a = p[0], b = p[1];
        const float f[8] = {a.x, a.y, a.z, a.w, b.x, b.y, b.z, b.w};
        __half h[8];
#pragma unroll
        for (int i = 0; i < 8; i++) h[i] = __float2half_rn(f[i]);
        *(uint4*)(g_we_h + base) = *(const uint4*)h;
    } else {
        __shared__ float sW[32 * 129];
        __shared__ float sH[32 * 129];
        const int bid2 = bid - 512;          // 0..255
        const int kc = bid2 & 7, ob = bid2 >> 3;
        const int o0 = ob * 32, k0 = kc * 128;
        const int ol = tid & 31;
        const int b0 = tid >> 5;
#pragma unroll
        for (int i = 0; i < 4; i++) {
            const int idx = tid + i * 256;            // 1024 float4 total
            const int row = idx >> 5, c4 = (idx & 31) * 4;
            const float4 w = *(const float4*)(W + (size_t)(o0 + row) * 2 * HDIM + k0 + c4);
            sW[row * 129 + c4 + 0] = w.x;
            sW[row * 129 + c4 + 1] = w.y;
            sW[row * 129 + c4 + 2] = w.z;
            sW[row * 129 + c4 + 3] = w.w;
            const float4 h = *(const float4*)(hidden + (size_t)row * HDIM + k0 + c4);
            sH[row * 129 + c4 + 0] = h.x;
            sH[row * 129 + c4 + 1] = h.y;
            sH[row * 129 + c4 + 2] = h.z;
            sH[row * 129 + c4 + 3] = h.w;
        }
        __syncthreads();
        float acc[4] = {0.f, 0.f, 0.f, 0.f};
#pragma unroll 4
        for (int k = 0; k < 128; k++) {
            const float w = sW[ol * 129 + k];
#pragma unroll
            for (int j = 0; j < 4; j++)
                acc[j] = fmaf(w, sH[(b0 + 8 * j) * 129 + k], acc[j]);
        }
        const float ba = (kc == 0) ? b_attn[o0 + ol] : 0.0f;
#pragma unroll
        for (int j = 0; j < 4; j++)
            g_bias_part[kc][(b0 + 8 * j) * HDIM + o0 + ol] = acc[j] + ba;
    }
}

// ---------------- gemm pieces ----------------
// A: thread (row = tid>>2, seg = tid&3) loads 8 fp32 of enc row
__device__ __forceinline__ void ldgA(float* af, const float* __restrict__ enc, int gs, int r0) {
    const int tid = threadIdx.x;
    const int row = tid >> 2, seg = tid & 3;
    const int k0 = (gs & 31) * 32;
    const float* p = enc + (size_t)(r0 + row) * HDIM + k0 + seg * 8;
    *(float4*)(af)     = *(const float4*)(p);
    *(float4*)(af + 4) = *(const float4*)(p + 4);
}
__device__ __forceinline__ void stsA(const float* af, char* smem, int gs) {
    const int tid = threadIdx.x;
    const int row = tid >> 2, seg = tid & 3;
    __half h[8];
#pragma unroll
    for (int i = 0; i < 8; i++) h[i] = __float2half_rn(af[i]);
    char* b = smem + (gs % NSTG) * STAGE_SZ + SA + row * STRIDE + seg * 16;
    *(uint4*)(b) = *(const uint4*)h;
}
__device__ __forceinline__ void cpB(uint32_t sb, int gs) {
    const int tid = threadIdx.x;
    const int k0 = (gs & 31) * 32, o0 = (gs >> 5) * NT;
    const uint32_t base = sb + (gs % NSTG) * STAGE_SZ + SB;
#pragma unroll
    for (int i = 0; i < 4; i++) {
        const int c = tid + i * 256;
        const int row = c >> 2, seg = c & 3;
        cp16(base + row * STRIDE + seg * 16,
             g_we_h + (size_t)(o0 + row) * HDIM + k0 + seg * 8);
    }
}

__global__ void __launch_bounds__(256, 2)
gemm_kernel(const float* __restrict__ enc, const float* __restrict__ v) {
    extern __shared__ char smem[];
    const uint32_t sb = smem_u32(smem);
    const int tid = threadIdx.x;
    const int lane = tid & 31, warp = tid >> 5;
    const int warp_m = (warp >> 2) * 32;      // 2 warps over M (2 mt of m16)
    const int warp_n = (warp & 3) * 64;       // 4 warps over N
    const int r0 = blockIdx.x * ROWS_CTA;
    const int bb = r0 >> 11;

    float* s_bias = (float*)(smem + SM_BIAS);
    float* s_v    = (float*)(smem + SM_V);
    float* s_row  = (float*)(smem + SM_ROW);
    for (int i = tid; i < HDIM; i += 256) {
        float bsum = 0.0f;
#pragma unroll
        for (int kc = 0; kc < 8; kc++)
            bsum += g_bias_part[kc][bb * HDIM + i];
        s_bias[i] = bsum;
        s_v[i] = v[i];
    }
    if (tid < ROWS_CTA) s_row[tid] = 0.0f;

    // ldmatrix per-lane address components
    const int q = lane >> 3, rr = lane & 7;
    const int a_row_off = (q & 1) * 8 + rr;
    const int a_k_off   = (q >> 1) * 8;
    const int b_row_off = (q >> 1) * 8 + rr;
    const int b_k_off   = (q & 1) * 8;

    float af[8];
    // prologue: stages 0,1 fully in flight; A(2) in regs
    ldgA(af, enc, 0, r0);
    stsA(af, smem, 0);
    ldgA(af, enc, 1, r0);
    stsA(af, smem, 1);
    cpB(sb, 0);
    asm volatile("cp.async.commit_group;" ::: "memory");
    cpB(sb, 1);
    asm volatile("cp.async.commit_group;" ::: "memory");
    ldgA(af, enc, 2, r0);

    float part[4] = {0.f, 0.f, 0.f, 0.f};
    float acc[2][8][4];

    for (int gs = 0; gs < GSTEPS; gs++) {
        asm volatile("cp.async.wait_group 1;" ::: "memory");
        __syncthreads();

        // issue next-stage traffic before compute (single sync per stage)
        if (gs + 2 < GSTEPS) stsA(af, smem, gs + 2);
        if (gs + 3 < GSTEPS) ldgA(af, enc, gs + 3, r0);
        if (gs + 2 < GSTEPS) cpB(sb, gs + 2);
        asm volatile("cp.async.commit_group;" ::: "memory");

        if ((gs & 31) == 0) {
#pragma unroll
            for (int mt = 0; mt < 2; mt++)
#pragma unroll
                for (int nt = 0; nt < 8; nt++)
#pragma unroll
                    for (int e = 0; e < 4; e++) acc[mt][nt][e] = 0.0f;
        }

        const uint32_t stg = sb + (uint32_t)(gs % NSTG) * STAGE_SZ;
        const uint32_t a_base = stg + SA;
        const uint32_t b_base = stg + SB + (warp_n + b_row_off) * STRIDE;
#pragma unroll
        for (int kh = 0; kh < 2; kh++) {
            const int kk = kh * 16;
            uint32_t ah[2][4];
#pragma unroll
            for (int mt = 0; mt < 2; mt++) {
                const uint32_t ra = a_base + (warp_m + mt * 16 + a_row_off) * STRIDE
                                  + (kk + a_k_off) * 2;
                ldsm4(ah[mt], ra);
            }
#pragma unroll
            for (int p = 0; p < 4; p++) {
                uint32_t bh[4];
                const uint32_t rb = b_base + p * 16 * STRIDE + (kk + b_k_off) * 2;
                ldsm4(bh, rb);
#pragma unroll
                for (int mt = 0; mt < 2; mt++) {
                    mma16816(acc[mt][2 * p],     ah[mt], bh);
                    mma16816(acc[mt][2 * p + 1], ah[mt], bh + 2);
                }
            }
        }

        if ((gs & 31) == 31) {
            const int oo = (gs >> 5) * NT + warp_n + (lane & 3) * 2;
#pragma unroll
            for (int mt = 0; mt < 2; mt++)
#pragma unroll
                for (int nt = 0; nt < 8; nt++) {
                    const int o0e = oo + nt * 8;
                    const float b0 = s_bias[o0e], b1 = s_bias[o0e + 1];
                    const float v0 = s_v[o0e],    v1 = s_v[o0e + 1];
                    const float* c = acc[mt][nt];
                    part[mt * 2 + 0] += ftanh(c[0] + b0) * v0 + ftanh(c[1] + b1) * v1;
                    part[mt * 2 + 1] += ftanh(c[2] + b0) * v0 + ftanh(c[3] + b1) * v1;
                }
        }
    }

    // reduce 4-lane groups sharing each row, then combine across n-warps
#pragma unroll
    for (int i = 0; i < 4; i++) {
        float s = part[i];
        s += __shfl_xor_sync(0xFFFFFFFFu, s, 1);
        s += __shfl_xor_sync(0xFFFFFFFFu, s, 2);
        if ((lane & 3) == 0) {
            const int row = warp_m + (i >> 1) * 16 + (i & 1) * 8 + (lane >> 2);
            atomicAdd(&s_row[row], s);
        }
    }
    __syncthreads();
    if (tid < ROWS_CTA) g_logits[r0 + tid] = s_row[tid];
}

// ---------------- softmax over s per batch (warp-shuffle reductions) ----------------
__global__ void softmax_kernel(float* __restrict__ out) {
    __shared__ float red[8];
    const int b = blockIdx.x, tid = threadIdx.x;
    const int lane = tid & 31, wid = tid >> 5;
    const float* lg = g_logits + (size_t)b * SDIM;
    float vals[8];
    float lmax = -1e30f;
#pragma unroll
    for (int i = 0; i < 8; i++) {
        vals[i] = lg[tid + i * 256];
        lmax = fmaxf(lmax, vals[i]);
    }
#pragma unroll
    for (int off = 16; off > 0; off >>= 1)
        lmax = fmaxf(lmax, __shfl_xor_sync(0xFFFFFFFFu, lmax, off));
    if (lane == 0) red[wid] = lmax;
    __syncthreads();
    float gmax = red[0];
#pragma unroll
    for (int w = 1; w < 8; w++) gmax = fmaxf(gmax, red[w]);

    float lsum = 0.0f;
#pragma unroll
    for (int i = 0; i < 8; i++) {
        vals[i] = expf(vals[i] - gmax);
        lsum += vals[i];
    }
#pragma unroll
    for (int off = 16; off > 0; off >>= 1)
        lsum += __shfl_xor_sync(0xFFFFFFFFu, lsum, off);
    __syncthreads();
    if (lane == 0) red[wid] = lsum;
    __syncthreads();
    float gsum = 0.0f;
#pragma unroll
    for (int w = 0; w < 8; w++) gsum += red[w];

    const float inv = 1.0f / gsum;
#pragma unroll
    for (int i = 0; i < 8; i++)
        out[(size_t)b * SDIM + tid + i * 256] = vals[i] * inv;
}

// ---------------- launch ----------------
extern "C" void kernel_launch(void* const* d_in, const int* in_sizes, int n_in,
                              void* d_out, int out_size) {
    const float* hidden = (const float*)d_in[0];
    const float* enc    = (const float*)d_in[1];
    const float* W      = (const float*)d_in[2];
    const float* b_attn = (const float*)d_in[3];
    const float* v      = (const float*)d_in[4];
    float* out = (float*)d_out;

    cudaFuncSetAttribute(gemm_kernel, cudaFuncAttributeMaxDynamicSharedMemorySize, SMEM_TOTAL);
    prep_kernel<<<768, 256>>>(W, hidden, b_attn);
    gemm_kernel<<<RDIM / ROWS_CTA, 256, SMEM_TOTAL>>>(enc, v);
    softmax_kernel<<<32, 256>>>(out);
}